// round 13
// baseline (speedup 1.0000x reference)
#include <cuda_runtime.h>
#include <math.h>

#define NP 768
#define DD 128
#define HH 8

// ---- scratch (no allocs allowed; static device globals) ----
__device__ float g_G [NP*NP];   // visual gram, later reused as edge "e" buffer ET
__device__ float g_G2[NP*NP];   // attribute gram
__device__ float g_VE[NP*NP];
__device__ float g_SE[NP*NP];
__device__ float g_P [NP*DD];
__device__ float g_M [NP*DD];
__device__ float g_S8[NP*HH];
__device__ float g_NR0[NP];
__device__ float g_NR1[NP];

// ====== symmetric X@X^T for both inputs in one launch (z=0 visual K=128, z=1 attr K=312)
// 64x64 tiles, 4x4 micro-tile per thread, upper block-triangle only, mirrored writes.
__global__ __launch_bounds__(256) void xxt_sym_kernel(const float* __restrict__ X0,
                                                      const float* __restrict__ X1,
                                                      float* __restrict__ G0,
                                                      float* __restrict__ G1) {
    if (blockIdx.x < blockIdx.y) return;
    int z = blockIdx.z;
    const float* __restrict__ X = z ? X1 : X0;
    float* __restrict__ G = z ? G1 : G0;
    const int K = z ? 312 : 128;

    __shared__ __align__(16) float Xi[16][68];
    __shared__ __align__(16) float Xk[16][68];

    int bi = blockIdx.y * 64, bk = blockIdx.x * 64;
    bool offDiag = (blockIdx.x > blockIdx.y);
    int t = threadIdx.x, tx = t & 15, ty = t >> 4;

    float acc[4][4];
#pragma unroll
    for (int r = 0; r < 4; r++)
#pragma unroll
        for (int c = 0; c < 4; c++) acc[r][c] = 0.f;

    for (int k0 = 0; k0 < K; k0 += 16) {
        for (int idx = t; idx < 1024; idx += 256) {
            int r = idx >> 4, c = idx & 15;
            int kc = k0 + c;
            Xi[c][r] = (kc < K) ? X[(bi + r) * K + kc] : 0.f;
            Xk[c][r] = (kc < K) ? X[(bk + r) * K + kc] : 0.f;
        }
        __syncthreads();
#pragma unroll
        for (int kk = 0; kk < 16; kk++) {
            float4 a = *(const float4*)&Xi[kk][4 * ty];
            float4 b = *(const float4*)&Xk[kk][4 * tx];
            acc[0][0] += a.x * b.x; acc[0][1] += a.x * b.y; acc[0][2] += a.x * b.z; acc[0][3] += a.x * b.w;
            acc[1][0] += a.y * b.x; acc[1][1] += a.y * b.y; acc[1][2] += a.y * b.z; acc[1][3] += a.y * b.w;
            acc[2][0] += a.z * b.x; acc[2][1] += a.z * b.y; acc[2][2] += a.z * b.z; acc[2][3] += a.z * b.w;
            acc[3][0] += a.w * b.x; acc[3][1] += a.w * b.y; acc[3][2] += a.w * b.z; acc[3][3] += a.w * b.w;
        }
        __syncthreads();
    }
    int gk = bk + 4 * tx;
#pragma unroll
    for (int r = 0; r < 4; r++) {
        int gi = bi + 4 * ty + r;
        *(float4*)&G[gi * NP + gk] = make_float4(acc[r][0], acc[r][1], acc[r][2], acc[r][3]);
        if (offDiag) {
            G[(gk + 0) * NP + gi] = acc[r][0];
            G[(gk + 1) * NP + gi] = acc[r][1];
            G[(gk + 2) * NP + gi] = acc[r][2];
            G[(gk + 3) * NP + gi] = acc[r][3];
        }
    }
}

__global__ void norms2_kernel(const float* __restrict__ G0, const float* __restrict__ G1,
                              float* __restrict__ n0, float* __restrict__ n1) {
    int i = blockIdx.x * 256 + threadIdx.x;
    if (i < NP) n0[i] = sqrtf(G0[i * NP + i]);
    else { int j = i - NP; if (j < NP) n1[j] = sqrtf(G1[j * NP + j]); }
}

// ====== cosine-sim softmax for both grams in one launch (grid 768 x 2) ======
__global__ __launch_bounds__(256) void softmax_sim2_kernel(const float* __restrict__ G0,
                                                           const float* __restrict__ G1,
                                                           const float* __restrict__ n0,
                                                           const float* __restrict__ n1,
                                                           float* __restrict__ E0,
                                                           float* __restrict__ E1) {
    __shared__ float sh[256];
    int z = blockIdx.y;
    const float* __restrict__ G = z ? G1 : G0;
    const float* __restrict__ nrm = z ? n1 : n0;
    float* __restrict__ E = z ? E1 : E0;
    const float invtemp = 10.0f;  // 1 / INIT_TEMP

    int i = blockIdx.x, t = threadIdx.x;
    float ni = nrm[i];
    float l[3];
    float mx = -1e30f;
#pragma unroll
    for (int q = 0; q < 3; q++) {
        int c = t + q * 256;
        float den = fmaxf(ni * nrm[c], 1e-8f);
        l[q] = G[i * NP + c] / den * invtemp;
        mx = fmaxf(mx, l[q]);
    }
    sh[t] = mx; __syncthreads();
    for (int s = 128; s > 0; s >>= 1) { if (t < s) sh[t] = fmaxf(sh[t], sh[t + s]); __syncthreads(); }
    mx = sh[0]; __syncthreads();
    float sum = 0.f;
#pragma unroll
    for (int q = 0; q < 3; q++) { l[q] = expf(l[q] - mx); sum += l[q]; }
    sh[t] = sum; __syncthreads();
    for (int s = 128; s > 0; s >>= 1) { if (t < s) sh[t] += sh[t + s]; __syncthreads(); }
    float inv = 1.f / sh[0];
#pragma unroll
    for (int q = 0; q < 3; q++) E[i * NP + t + q * 256] = l[q] * inv;
}

// ====== edge softmax: logits = e * (last + eps) * invtemp, fused ======
__global__ __launch_bounds__(256) void softmax_edge_kernel(const float* __restrict__ ET,
                                                           const float* __restrict__ LAST,
                                                           float invtemp,
                                                           float* __restrict__ E) {
    __shared__ float sh[256];
    int i = blockIdx.x, t = threadIdx.x;
    float l[3];
    float mx = -1e30f;
#pragma unroll
    for (int q = 0; q < 3; q++) {
        int c = i * NP + t + q * 256;
        l[q] = ET[c] * (LAST[c] + 1e-8f) * invtemp;
        mx = fmaxf(mx, l[q]);
    }
    sh[t] = mx; __syncthreads();
    for (int s = 128; s > 0; s >>= 1) { if (t < s) sh[t] = fmaxf(sh[t], sh[t + s]); __syncthreads(); }
    mx = sh[0]; __syncthreads();
    float sum = 0.f;
#pragma unroll
    for (int q = 0; q < 3; q++) { l[q] = expf(l[q] - mx); sum += l[q]; }
    sh[t] = sum; __syncthreads();
    for (int s = 128; s > 0; s >>= 1) { if (t < s) sh[t] += sh[t + s]; __syncthreads(); }
    float inv = 1.f / sh[0];
#pragma unroll
    for (int q = 0; q < 3; q++) E[i * NP + t + q * 256] = l[q] * inv;
}

// ===== aggregation v3: P = E @ V ; M = (E + L) @ V =====
// grid = 96, block 256. Block owns 8 output rows x 128 cols.
// Thread = 8 rows x 1 col; 2 K-phases (warps 0-3: k<384, warps 4-7: k>=384),
// V read directly from L2 via coalesced __ldg (no smem staging),
// E/(E+L) transposed in smem [768][8] -> 2x LDS.128 broadcast per k.
__global__ __launch_bounds__(256) void agg_kernel(const float* __restrict__ E,
                                                  const float* __restrict__ L,
                                                  const float* __restrict__ V,
                                                  float* __restrict__ Pout,
                                                  float* __restrict__ Mout) {
    __shared__ __align__(16) float SM[2 * NP * 8];   // 48KB: Et [768][8] | St [768][8]
    float (*Et)[8] = (float(*)[8])SM;
    float (*St)[8] = (float(*)[8])(SM + NP * 8);

    int bi = blockIdx.x * 8;
    int t = threadIdx.x;
    int col = t & 127;
    int phase = t >> 7;          // 0 or 1

    // preload E/L rows transposed, S = E + L (coalesced global reads)
#pragma unroll
    for (int r = 0; r < 8; r++) {
        for (int k = t; k < NP; k += 256) {
            float e = E[(bi + r) * NP + k];
            float l = L[(bi + r) * NP + k];
            Et[k][r] = e;
            St[k][r] = e + l;
        }
    }
    __syncthreads();

    float p[8], m[8];
#pragma unroll
    for (int r = 0; r < 8; r++) { p[r] = 0.f; m[r] = 0.f; }

    int k0 = phase * (NP / 2);
    const float* __restrict__ vp = V + col;
#pragma unroll 4
    for (int k = k0; k < k0 + NP / 2; k++) {
        float v = __ldg(vp + k * DD);
        float4 e0 = *(const float4*)&Et[k][0];
        float4 e1 = *(const float4*)&Et[k][4];
        float4 s0 = *(const float4*)&St[k][0];
        float4 s1 = *(const float4*)&St[k][4];
        p[0] += e0.x * v; p[1] += e0.y * v; p[2] += e0.z * v; p[3] += e0.w * v;
        p[4] += e1.x * v; p[5] += e1.y * v; p[6] += e1.z * v; p[7] += e1.w * v;
        m[0] += s0.x * v; m[1] += s0.y * v; m[2] += s0.z * v; m[3] += s0.w * v;
        m[4] += s1.x * v; m[5] += s1.y * v; m[6] += s1.z * v; m[7] += s1.w * v;
    }

    // 2-way cross-phase reduction; reuse SM (Et/St no longer needed)
    __syncthreads();
    float* RedP = SM;              // [8][128]
    float* RedM = SM + 1024;       // [8][128]
    if (phase == 1) {
#pragma unroll
        for (int r = 0; r < 8; r++) {
            RedP[r * 128 + col] = p[r];
            RedM[r * 128 + col] = m[r];
        }
    }
    __syncthreads();
    if (phase == 0) {
#pragma unroll
        for (int r = 0; r < 8; r++) {
            Pout[(bi + r) * DD + col] = p[r] + RedP[r * 128 + col];
            Mout[(bi + r) * DD + col] = m[r] + RedM[r * 128 + col];
        }
    }
}

// ======== node update: out = relu(LN(M @ W^T + b, g, beta)) + P  ========
__global__ __launch_bounds__(128) void node_kernel(const float* __restrict__ Mi,
                                                   const float* __restrict__ Pi,
                                                   const float* __restrict__ W,
                                                   const float* __restrict__ bv,
                                                   const float* __restrict__ gv,
                                                   const float* __restrict__ bev,
                                                   float* __restrict__ outp) {
    __shared__ float ms[128];
    __shared__ float red[128];
    int i = blockIdx.x, o = threadIdx.x;
    ms[o] = Mi[i * DD + o];
    __syncthreads();
    float acc = bv[o];
    const float4* w4 = (const float4*)(W + o * DD);
    const float4* m4 = (const float4*)ms;
#pragma unroll
    for (int q = 0; q < 32; q++) {
        float4 w = w4[q];
        float4 m = m4[q];
        acc += w.x * m.x + w.y * m.y + w.z * m.z + w.w * m.w;
    }
    red[o] = acc; __syncthreads();
    for (int s = 64; s > 0; s >>= 1) { if (o < s) red[o] += red[o + s]; __syncthreads(); }
    float mean = red[0] * (1.f / 128.f); __syncthreads();
    float dv = acc - mean;
    red[o] = dv * dv; __syncthreads();
    for (int s = 64; s > 0; s >>= 1) { if (o < s) red[o] += red[o + s]; __syncthreads(); }
    float var = red[0] * (1.f / 128.f);
    float y = dv / sqrtf(var + 1e-5f) * gv[o] + bev[o];
    outp[i * DD + o] = fmaxf(y, 0.f) + Pi[i * DD + o];
}

// ========== S[i][j] = sum_d proto[i][d]^2 * W1[j][d]  (for edge MLP) ==========
__global__ __launch_bounds__(128) void s8_kernel(const float* __restrict__ Pp,
                                                 const float* __restrict__ W1,
                                                 float* __restrict__ S) {
    __shared__ float red[8][128];
    int i = blockIdx.x, t = threadIdx.x;
    float a = Pp[i * DD + t];
    float a2 = a * a;
#pragma unroll
    for (int j = 0; j < 8; j++) red[j][t] = a2 * W1[j * DD + t];
    __syncthreads();
    for (int s = 64; s > 0; s >>= 1) {
        if (t < s) {
#pragma unroll
            for (int j = 0; j < 8; j++) red[j][t] += red[j][t + s];
        }
        __syncthreads();
    }
    if (t < 8) S[i * HH + t] = red[t][0];
}

// ======= fused edge MLP (symmetric: upper block-triangle only) =======
// writes e = tanh(MLP(pairwise sqdiff)) to ET (symmetric, mirrored)
__global__ __launch_bounds__(256) void edge_mlp_kernel(const float* __restrict__ Pp,
                                                       const float* __restrict__ W1,
                                                       const float* __restrict__ b1,
                                                       const float* __restrict__ W2,
                                                       const float* __restrict__ b2v,
                                                       const float* __restrict__ S,
                                                       float* __restrict__ ET) {
    if (blockIdx.x < blockIdx.y) return;

    __shared__ float Ais[128][33];   // [d][i] transposed tiles
    __shared__ float Aks[128][33];
    __shared__ __align__(16) float W1s[128][8];    // [d][j]
    __shared__ float Sis[32][8];
    __shared__ float Sks[32][8];
    __shared__ float W2s[8];
    __shared__ float b1s[8];
    __shared__ float b2s;

    int bi = blockIdx.y * 32, bk = blockIdx.x * 32;
    bool offDiag = (blockIdx.x > blockIdx.y);
    int t = threadIdx.x;
    for (int idx = t; idx < 4096; idx += 256) {
        int r = idx >> 7, c = idx & 127;
        Ais[c][r] = Pp[(bi + r) * DD + c];
        Aks[c][r] = Pp[(bk + r) * DD + c];
    }
    for (int idx = t; idx < HH * DD; idx += 256)
        W1s[idx & 127][idx >> 7] = W1[idx];
    {
        int r = t >> 3, j = t & 7;
        Sis[r][j] = S[(bi + r) * HH + j];
        Sks[r][j] = S[(bk + r) * HH + j];
    }
    if (t < 8) { W2s[t] = W2[t]; b1s[t] = b1[t]; }
    if (t == 0) b2s = b2v[0];
    __syncthreads();

    int tx = t & 15, ty = t >> 4;
    int i0 = 2 * ty, k0 = 2 * tx;
    float acc[2][2][8];
#pragma unroll
    for (int a = 0; a < 2; a++)
#pragma unroll
        for (int b = 0; b < 2; b++)
#pragma unroll
            for (int j = 0; j < 8; j++) acc[a][b][j] = 0.f;

#pragma unroll 4
    for (int d = 0; d < 128; d++) {
        float4 wa = *(const float4*)&W1s[d][0];
        float4 wb = *(const float4*)&W1s[d][4];
        float w[8] = {wa.x, wa.y, wa.z, wa.w, wb.x, wb.y, wb.z, wb.w};
        float ai0 = Ais[d][i0], ai1 = Ais[d][i0 + 1];
        float ak0 = Aks[d][k0], ak1 = Aks[d][k0 + 1];
        float p00 = ai0 * ak0, p01 = ai0 * ak1;
        float p10 = ai1 * ak0, p11 = ai1 * ak1;
#pragma unroll
        for (int j = 0; j < 8; j++) {
            acc[0][0][j] += p00 * w[j];
            acc[0][1][j] += p01 * w[j];
            acc[1][0][j] += p10 * w[j];
            acc[1][1][j] += p11 * w[j];
        }
    }

#pragma unroll
    for (int ii = 0; ii < 2; ii++)
#pragma unroll
        for (int kk = 0; kk < 2; kk++) {
            int gi = bi + i0 + ii, gk = bk + k0 + kk;
            bool diag = (gi == gk);
            float h[8];
            float mean = 0.f;
#pragma unroll
            for (int j = 0; j < 8; j++) {
                float v = diag ? b1s[j]
                               : (Sis[i0 + ii][j] + Sks[k0 + kk][j] - 2.f * acc[ii][kk][j] + b1s[j]);
                h[j] = v;
                mean += v;
            }
            mean *= 0.125f;
            float var = 0.f;
#pragma unroll
            for (int j = 0; j < 8; j++) { float dv = h[j] - mean; var += dv * dv; }
            var *= 0.125f;
            float inv = 1.f / sqrtf(var + 1e-5f);
            float sdot = b2s;
#pragma unroll
            for (int j = 0; j < 8; j++) {
                float r = fmaxf((h[j] - mean) * inv, 0.f);
                sdot += r * W2s[j];
            }
            float e = tanhf(sdot);
            ET[gi * NP + gk] = e;
            if (offDiag) ET[gk * NP + gi] = e;
        }
}

// ============================== launcher ==============================
extern "C" void kernel_launch(void* const* d_in, const int* in_sizes, int n_in,
                              void* d_out, int out_size) {
    const float* visual   = (const float*)d_in[0];
    const float* semantic = (const float*)d_in[1];
    const float* attr     = (const float*)d_in[2];
    const float* Wvn  = (const float*)d_in[3];
    const float* bvn  = (const float*)d_in[4];
    const float* gvn  = (const float*)d_in[5];
    const float* betavn = (const float*)d_in[6];
    const float* Wve1 = (const float*)d_in[7];
    const float* bve1 = (const float*)d_in[8];
    const float* Wve2 = (const float*)d_in[9];
    const float* bve2 = (const float*)d_in[10];
    const float* Wsn  = (const float*)d_in[11];
    const float* bsn  = (const float*)d_in[12];
    const float* gsn  = (const float*)d_in[13];
    const float* betasn = (const float*)d_in[14];
    const float* Wse1 = (const float*)d_in[15];
    const float* bse1 = (const float*)d_in[16];
    const float* Wse2 = (const float*)d_in[17];
    const float* bse2 = (const float*)d_in[18];

    float* out = (float*)d_out;
    float* vp  = out;                       // [768,128]
    float* sp  = out + NP * DD;             // [768,128]
    float* ve2 = out + 2 * NP * DD;         // [768,768]
    float* se2 = ve2 + NP * NP;             // [768,768]

    float *G, *G2, *VE, *SE, *P, *M, *S8, *NR0, *NR1;
    cudaGetSymbolAddress((void**)&G,   g_G);
    cudaGetSymbolAddress((void**)&G2,  g_G2);
    cudaGetSymbolAddress((void**)&VE,  g_VE);
    cudaGetSymbolAddress((void**)&SE,  g_SE);
    cudaGetSymbolAddress((void**)&P,   g_P);
    cudaGetSymbolAddress((void**)&M,   g_M);
    cudaGetSymbolAddress((void**)&S8,  g_S8);
    cudaGetSymbolAddress((void**)&NR0, g_NR0);
    cudaGetSymbolAddress((void**)&NR1, g_NR1);

    float* ET = G;  // reuse visual gram buffer once VE is computed

    // ve = init_edge(visual, 0.1); se = init_edge(attribute, 0.1) — fused launches
    xxt_sym_kernel<<<dim3(12, 12, 2), 256>>>(visual, attr, G, G2);
    norms2_kernel<<<6, 256>>>(G, G2, NR0, NR1);
    softmax_sim2_kernel<<<dim3(NP, 2), 256>>>(G, G2, NR0, NR1, VE, SE);

    // vp = node_update(visual, last=se, edge=ve)
    agg_kernel<<<96, 256>>>(VE, SE, visual, P, M);
    node_kernel<<<NP, 128>>>(M, P, Wvn, bvn, gvn, betavn, vp);

    // ve2 = edge_update(vp, ve, temp=10)
    s8_kernel<<<NP, 128>>>(vp, Wve1, S8);
    edge_mlp_kernel<<<dim3(24, 24), 256>>>(vp, Wve1, bve1, Wve2, bve2, S8, ET);
    softmax_edge_kernel<<<NP, 256>>>(ET, VE, 0.1f, ve2);

    // sp = node_update(semantic, last=ve2, edge=se)
    agg_kernel<<<96, 256>>>(SE, ve2, semantic, P, M);
    node_kernel<<<NP, 128>>>(M, P, Wsn, bsn, gsn, betasn, sp);

    // se2 = edge_update(sp, se, temp=10)
    s8_kernel<<<NP, 128>>>(sp, Wse1, S8);
    edge_mlp_kernel<<<dim3(24, 24), 256>>>(sp, Wse1, bse1, Wse2, bse2, S8, ET);
    softmax_edge_kernel<<<NP, 256>>>(ET, SE, 0.1f, se2);
}

// round 14
// speedup vs baseline: 1.7456x; 1.7456x over previous
#include <cuda_runtime.h>
#include <math.h>

#define NP 768
#define DD 128
#define HH 8
#define KSPLIT 4
#define KRANGE (NP / KSPLIT)   // 192

// ---- scratch (no allocs allowed; static device globals) ----
__device__ float g_G [NP*NP];   // visual gram, later reused as edge "e" buffer ET
__device__ float g_G2[NP*NP];   // attribute gram
__device__ float g_VE[NP*NP];
__device__ float g_SE[NP*NP];
__device__ float g_Pp[KSPLIT*NP*DD];   // split-K partials for P
__device__ float g_Mp[KSPLIT*NP*DD];   // split-K partials for M
__device__ float g_S8[NP*HH];
__device__ float g_NR0[NP];
__device__ float g_NR1[NP];

// ====== symmetric X@X^T for both inputs in one launch (z=0 visual K=128, z=1 attr K=312)
// 64x64 tiles, 4x4 micro-tile per thread, upper block-triangle only, mirrored writes.
__global__ __launch_bounds__(256) void xxt_sym_kernel(const float* __restrict__ X0,
                                                      const float* __restrict__ X1,
                                                      float* __restrict__ G0,
                                                      float* __restrict__ G1) {
    if (blockIdx.x < blockIdx.y) return;
    int z = blockIdx.z;
    const float* __restrict__ X = z ? X1 : X0;
    float* __restrict__ G = z ? G1 : G0;
    const int K = z ? 312 : 128;

    __shared__ __align__(16) float Xi[16][68];
    __shared__ __align__(16) float Xk[16][68];

    int bi = blockIdx.y * 64, bk = blockIdx.x * 64;
    bool offDiag = (blockIdx.x > blockIdx.y);
    int t = threadIdx.x, tx = t & 15, ty = t >> 4;

    float acc[4][4];
#pragma unroll
    for (int r = 0; r < 4; r++)
#pragma unroll
        for (int c = 0; c < 4; c++) acc[r][c] = 0.f;

    for (int k0 = 0; k0 < K; k0 += 16) {
        for (int idx = t; idx < 1024; idx += 256) {
            int r = idx >> 4, c = idx & 15;
            int kc = k0 + c;
            Xi[c][r] = (kc < K) ? X[(bi + r) * K + kc] : 0.f;
            Xk[c][r] = (kc < K) ? X[(bk + r) * K + kc] : 0.f;
        }
        __syncthreads();
#pragma unroll
        for (int kk = 0; kk < 16; kk++) {
            float4 a = *(const float4*)&Xi[kk][4 * ty];
            float4 b = *(const float4*)&Xk[kk][4 * tx];
            acc[0][0] += a.x * b.x; acc[0][1] += a.x * b.y; acc[0][2] += a.x * b.z; acc[0][3] += a.x * b.w;
            acc[1][0] += a.y * b.x; acc[1][1] += a.y * b.y; acc[1][2] += a.y * b.z; acc[1][3] += a.y * b.w;
            acc[2][0] += a.z * b.x; acc[2][1] += a.z * b.y; acc[2][2] += a.z * b.z; acc[2][3] += a.z * b.w;
            acc[3][0] += a.w * b.x; acc[3][1] += a.w * b.y; acc[3][2] += a.w * b.z; acc[3][3] += a.w * b.w;
        }
        __syncthreads();
    }
    int gk = bk + 4 * tx;
#pragma unroll
    for (int r = 0; r < 4; r++) {
        int gi = bi + 4 * ty + r;
        *(float4*)&G[gi * NP + gk] = make_float4(acc[r][0], acc[r][1], acc[r][2], acc[r][3]);
        if (offDiag) {
            G[(gk + 0) * NP + gi] = acc[r][0];
            G[(gk + 1) * NP + gi] = acc[r][1];
            G[(gk + 2) * NP + gi] = acc[r][2];
            G[(gk + 3) * NP + gi] = acc[r][3];
        }
    }
}

__global__ void norms2_kernel(const float* __restrict__ G0, const float* __restrict__ G1,
                              float* __restrict__ n0, float* __restrict__ n1) {
    int i = blockIdx.x * 256 + threadIdx.x;
    if (i < NP) n0[i] = sqrtf(G0[i * NP + i]);
    else { int j = i - NP; if (j < NP) n1[j] = sqrtf(G1[j * NP + j]); }
}

// ====== cosine-sim softmax for both grams in one launch (grid 768 x 2) ======
__global__ __launch_bounds__(256) void softmax_sim2_kernel(const float* __restrict__ G0,
                                                           const float* __restrict__ G1,
                                                           const float* __restrict__ n0,
                                                           const float* __restrict__ n1,
                                                           float* __restrict__ E0,
                                                           float* __restrict__ E1) {
    __shared__ float sh[256];
    int z = blockIdx.y;
    const float* __restrict__ G = z ? G1 : G0;
    const float* __restrict__ nrm = z ? n1 : n0;
    float* __restrict__ E = z ? E1 : E0;
    const float invtemp = 10.0f;  // 1 / INIT_TEMP

    int i = blockIdx.x, t = threadIdx.x;
    float ni = nrm[i];
    float l[3];
    float mx = -1e30f;
#pragma unroll
    for (int q = 0; q < 3; q++) {
        int c = t + q * 256;
        float den = fmaxf(ni * nrm[c], 1e-8f);
        l[q] = G[i * NP + c] / den * invtemp;
        mx = fmaxf(mx, l[q]);
    }
    sh[t] = mx; __syncthreads();
    for (int s = 128; s > 0; s >>= 1) { if (t < s) sh[t] = fmaxf(sh[t], sh[t + s]); __syncthreads(); }
    mx = sh[0]; __syncthreads();
    float sum = 0.f;
#pragma unroll
    for (int q = 0; q < 3; q++) { l[q] = expf(l[q] - mx); sum += l[q]; }
    sh[t] = sum; __syncthreads();
    for (int s = 128; s > 0; s >>= 1) { if (t < s) sh[t] += sh[t + s]; __syncthreads(); }
    float inv = 1.f / sh[0];
#pragma unroll
    for (int q = 0; q < 3; q++) E[i * NP + t + q * 256] = l[q] * inv;
}

// ====== edge softmax: logits = e * (last + eps) * invtemp, fused ======
__global__ __launch_bounds__(256) void softmax_edge_kernel(const float* __restrict__ ET,
                                                           const float* __restrict__ LAST,
                                                           float invtemp,
                                                           float* __restrict__ E) {
    __shared__ float sh[256];
    int i = blockIdx.x, t = threadIdx.x;
    float l[3];
    float mx = -1e30f;
#pragma unroll
    for (int q = 0; q < 3; q++) {
        int c = i * NP + t + q * 256;
        l[q] = ET[c] * (LAST[c] + 1e-8f) * invtemp;
        mx = fmaxf(mx, l[q]);
    }
    sh[t] = mx; __syncthreads();
    for (int s = 128; s > 0; s >>= 1) { if (t < s) sh[t] = fmaxf(sh[t], sh[t + s]); __syncthreads(); }
    mx = sh[0]; __syncthreads();
    float sum = 0.f;
#pragma unroll
    for (int q = 0; q < 3; q++) { l[q] = expf(l[q] - mx); sum += l[q]; }
    sh[t] = sum; __syncthreads();
    for (int s = 128; s > 0; s >>= 1) { if (t < s) sh[t] += sh[t + s]; __syncthreads(); }
    float inv = 1.f / sh[0];
#pragma unroll
    for (int q = 0; q < 3; q++) E[i * NP + t + q * 256] = l[q] * inv;
}

// ===== aggregation v4: split-K version of the proven v2 loop =====
// grid (96, KSPLIT). Block = 8 rows x 128 cols over K-range 192.
// Smem 46.6KB -> 4 blocks/SM. Partials written to Ppart/Mpart[ blockIdx.y ].
__global__ __launch_bounds__(256) void agg_kernel(const float* __restrict__ E,
                                                  const float* __restrict__ L,
                                                  const float* __restrict__ V,
                                                  float* __restrict__ Ppart,
                                                  float* __restrict__ Mpart) {
    __shared__ float Et[KRANGE][9];               // [k][row], pad 9
    __shared__ float St[KRANGE][9];               // E + L
    __shared__ __align__(16) float Vs[64][128];

    int bi = blockIdx.x * 8;
    int kb = blockIdx.y * KRANGE;
    int t = threadIdx.x;
    int tx = t & 31;          // col group: 4 cols each -> 128 cols
    int ty = t >> 5;          // row 0..7 (uniform per warp -> smem broadcast reads)

    // preload E/L rows for this block's K-range, transposed, S = E + L
#pragma unroll
    for (int r = 0; r < 8; r++) {
        for (int k = t; k < KRANGE; k += 256) {
            float e = E[(bi + r) * NP + kb + k];
            float l = L[(bi + r) * NP + kb + k];
            Et[k][r] = e;
            St[k][r] = e + l;
        }
    }

    float4 p = make_float4(0.f, 0.f, 0.f, 0.f);
    float4 m = make_float4(0.f, 0.f, 0.f, 0.f);

    for (int c = 0; c < KRANGE; c += 64) {
        __syncthreads();
        // load V chunk [64][128]
        for (int idx = t; idx < 2048; idx += 256) {
            int kk = idx >> 5, c4 = idx & 31;
            *(float4*)&Vs[kk][c4 * 4] = *(const float4*)&V[(kb + c + kk) * DD + c4 * 4];
        }
        __syncthreads();
#pragma unroll 16
        for (int kk = 0; kk < 64; kk++) {
            float e = Et[c + kk][ty];
            float s = St[c + kk][ty];
            float4 v = *(const float4*)&Vs[kk][4 * tx];
            p.x += e * v.x; p.y += e * v.y; p.z += e * v.z; p.w += e * v.w;
            m.x += s * v.x; m.y += s * v.y; m.z += s * v.z; m.w += s * v.w;
        }
    }
    int row = bi + ty, col = 4 * tx;
    int off = blockIdx.y * NP * DD + row * DD + col;
    *(float4*)&Ppart[off] = p;
    *(float4*)&Mpart[off] = m;
}

// ======== node update: out = relu(LN(M @ W^T + b, g, beta)) + P  ========
// Mi/Pi are KSPLIT-way split-K partials (stride NP*DD); summed here.
__global__ __launch_bounds__(128) void node_kernel(const float* __restrict__ Mi,
                                                   const float* __restrict__ Pi,
                                                   const float* __restrict__ W,
                                                   const float* __restrict__ bv,
                                                   const float* __restrict__ gv,
                                                   const float* __restrict__ bev,
                                                   float* __restrict__ outp) {
    __shared__ float ms[128];
    __shared__ float red[128];
    int i = blockIdx.x, o = threadIdx.x;
    int idx = i * DD + o;
    float mval = Mi[idx] + Mi[idx + NP*DD] + Mi[idx + 2*NP*DD] + Mi[idx + 3*NP*DD];
    float pval = Pi[idx] + Pi[idx + NP*DD] + Pi[idx + 2*NP*DD] + Pi[idx + 3*NP*DD];
    ms[o] = mval;
    __syncthreads();
    float acc = bv[o];
    const float4* w4 = (const float4*)(W + o * DD);
    const float4* m4 = (const float4*)ms;
#pragma unroll
    for (int q = 0; q < 32; q++) {
        float4 w = w4[q];
        float4 m = m4[q];
        acc += w.x * m.x + w.y * m.y + w.z * m.z + w.w * m.w;
    }
    red[o] = acc; __syncthreads();
    for (int s = 64; s > 0; s >>= 1) { if (o < s) red[o] += red[o + s]; __syncthreads(); }
    float mean = red[0] * (1.f / 128.f); __syncthreads();
    float dv = acc - mean;
    red[o] = dv * dv; __syncthreads();
    for (int s = 64; s > 0; s >>= 1) { if (o < s) red[o] += red[o + s]; __syncthreads(); }
    float var = red[0] * (1.f / 128.f);
    float y = dv / sqrtf(var + 1e-5f) * gv[o] + bev[o];
    outp[i * DD + o] = fmaxf(y, 0.f) + pval;
}

// ========== S[i][j] = sum_d proto[i][d]^2 * W1[j][d]  (for edge MLP) ==========
__global__ __launch_bounds__(128) void s8_kernel(const float* __restrict__ Pp,
                                                 const float* __restrict__ W1,
                                                 float* __restrict__ S) {
    __shared__ float red[8][128];
    int i = blockIdx.x, t = threadIdx.x;
    float a = Pp[i * DD + t];
    float a2 = a * a;
#pragma unroll
    for (int j = 0; j < 8; j++) red[j][t] = a2 * W1[j * DD + t];
    __syncthreads();
    for (int s = 64; s > 0; s >>= 1) {
        if (t < s) {
#pragma unroll
            for (int j = 0; j < 8; j++) red[j][t] += red[j][t + s];
        }
        __syncthreads();
    }
    if (t < 8) S[i * HH + t] = red[t][0];
}

// ======= fused edge MLP (symmetric: upper block-triangle only) =======
// writes e = tanh(MLP(pairwise sqdiff)) to ET (symmetric, mirrored)
__global__ __launch_bounds__(256) void edge_mlp_kernel(const float* __restrict__ Pp,
                                                       const float* __restrict__ W1,
                                                       const float* __restrict__ b1,
                                                       const float* __restrict__ W2,
                                                       const float* __restrict__ b2v,
                                                       const float* __restrict__ S,
                                                       float* __restrict__ ET) {
    if (blockIdx.x < blockIdx.y) return;

    __shared__ float Ais[128][33];   // [d][i] transposed tiles
    __shared__ float Aks[128][33];
    __shared__ __align__(16) float W1s[128][8];    // [d][j]
    __shared__ float Sis[32][8];
    __shared__ float Sks[32][8];
    __shared__ float W2s[8];
    __shared__ float b1s[8];
    __shared__ float b2s;

    int bi = blockIdx.y * 32, bk = blockIdx.x * 32;
    bool offDiag = (blockIdx.x > blockIdx.y);
    int t = threadIdx.x;
    for (int idx = t; idx < 4096; idx += 256) {
        int r = idx >> 7, c = idx & 127;
        Ais[c][r] = Pp[(bi + r) * DD + c];
        Aks[c][r] = Pp[(bk + r) * DD + c];
    }
    for (int idx = t; idx < HH * DD; idx += 256)
        W1s[idx & 127][idx >> 7] = W1[idx];
    {
        int r = t >> 3, j = t & 7;
        Sis[r][j] = S[(bi + r) * HH + j];
        Sks[r][j] = S[(bk + r) * HH + j];
    }
    if (t < 8) { W2s[t] = W2[t]; b1s[t] = b1[t]; }
    if (t == 0) b2s = b2v[0];
    __syncthreads();

    int tx = t & 15, ty = t >> 4;
    int i0 = 2 * ty, k0 = 2 * tx;
    float acc[2][2][8];
#pragma unroll
    for (int a = 0; a < 2; a++)
#pragma unroll
        for (int b = 0; b < 2; b++)
#pragma unroll
            for (int j = 0; j < 8; j++) acc[a][b][j] = 0.f;

#pragma unroll 4
    for (int d = 0; d < 128; d++) {
        float4 wa = *(const float4*)&W1s[d][0];
        float4 wb = *(const float4*)&W1s[d][4];
        float w[8] = {wa.x, wa.y, wa.z, wa.w, wb.x, wb.y, wb.z, wb.w};
        float ai0 = Ais[d][i0], ai1 = Ais[d][i0 + 1];
        float ak0 = Aks[d][k0], ak1 = Aks[d][k0 + 1];
        float p00 = ai0 * ak0, p01 = ai0 * ak1;
        float p10 = ai1 * ak0, p11 = ai1 * ak1;
#pragma unroll
        for (int j = 0; j < 8; j++) {
            acc[0][0][j] += p00 * w[j];
            acc[0][1][j] += p01 * w[j];
            acc[1][0][j] += p10 * w[j];
            acc[1][1][j] += p11 * w[j];
        }
    }

#pragma unroll
    for (int ii = 0; ii < 2; ii++)
#pragma unroll
        for (int kk = 0; kk < 2; kk++) {
            int gi = bi + i0 + ii, gk = bk + k0 + kk;
            bool diag = (gi == gk);
            float h[8];
            float mean = 0.f;
#pragma unroll
            for (int j = 0; j < 8; j++) {
                float v = diag ? b1s[j]
                               : (Sis[i0 + ii][j] + Sks[k0 + kk][j] - 2.f * acc[ii][kk][j] + b1s[j]);
                h[j] = v;
                mean += v;
            }
            mean *= 0.125f;
            float var = 0.f;
#pragma unroll
            for (int j = 0; j < 8; j++) { float dv = h[j] - mean; var += dv * dv; }
            var *= 0.125f;
            float inv = 1.f / sqrtf(var + 1e-5f);
            float sdot = b2s;
#pragma unroll
            for (int j = 0; j < 8; j++) {
                float r = fmaxf((h[j] - mean) * inv, 0.f);
                sdot += r * W2s[j];
            }
            float e = tanhf(sdot);
            ET[gi * NP + gk] = e;
            if (offDiag) ET[gk * NP + gi] = e;
        }
}

// ============================== launcher ==============================
extern "C" void kernel_launch(void* const* d_in, const int* in_sizes, int n_in,
                              void* d_out, int out_size) {
    const float* visual   = (const float*)d_in[0];
    const float* semantic = (const float*)d_in[1];
    const float* attr     = (const float*)d_in[2];
    const float* Wvn  = (const float*)d_in[3];
    const float* bvn  = (const float*)d_in[4];
    const float* gvn  = (const float*)d_in[5];
    const float* betavn = (const float*)d_in[6];
    const float* Wve1 = (const float*)d_in[7];
    const float* bve1 = (const float*)d_in[8];
    const float* Wve2 = (const float*)d_in[9];
    const float* bve2 = (const float*)d_in[10];
    const float* Wsn  = (const float*)d_in[11];
    const float* bsn  = (const float*)d_in[12];
    const float* gsn  = (const float*)d_in[13];
    const float* betasn = (const float*)d_in[14];
    const float* Wse1 = (const float*)d_in[15];
    const float* bse1 = (const float*)d_in[16];
    const float* Wse2 = (const float*)d_in[17];
    const float* bse2 = (const float*)d_in[18];

    float* out = (float*)d_out;
    float* vp  = out;                       // [768,128]
    float* sp  = out + NP * DD;             // [768,128]
    float* ve2 = out + 2 * NP * DD;         // [768,768]
    float* se2 = ve2 + NP * NP;             // [768,768]

    float *G, *G2, *VE, *SE, *Pp, *Mp, *S8, *NR0, *NR1;
    cudaGetSymbolAddress((void**)&G,   g_G);
    cudaGetSymbolAddress((void**)&G2,  g_G2);
    cudaGetSymbolAddress((void**)&VE,  g_VE);
    cudaGetSymbolAddress((void**)&SE,  g_SE);
    cudaGetSymbolAddress((void**)&Pp,  g_Pp);
    cudaGetSymbolAddress((void**)&Mp,  g_Mp);
    cudaGetSymbolAddress((void**)&S8,  g_S8);
    cudaGetSymbolAddress((void**)&NR0, g_NR0);
    cudaGetSymbolAddress((void**)&NR1, g_NR1);

    float* ET = G;  // reuse visual gram buffer once VE is computed

    // ve = init_edge(visual, 0.1); se = init_edge(attribute, 0.1) — fused launches
    xxt_sym_kernel<<<dim3(12, 12, 2), 256>>>(visual, attr, G, G2);
    norms2_kernel<<<6, 256>>>(G, G2, NR0, NR1);
    softmax_sim2_kernel<<<dim3(NP, 2), 256>>>(G, G2, NR0, NR1, VE, SE);

    // vp = node_update(visual, last=se, edge=ve)
    agg_kernel<<<dim3(96, KSPLIT), 256>>>(VE, SE, visual, Pp, Mp);
    node_kernel<<<NP, 128>>>(Mp, Pp, Wvn, bvn, gvn, betavn, vp);

    // ve2 = edge_update(vp, ve, temp=10)
    s8_kernel<<<NP, 128>>>(vp, Wve1, S8);
    edge_mlp_kernel<<<dim3(24, 24), 256>>>(vp, Wve1, bve1, Wve2, bve2, S8, ET);
    softmax_edge_kernel<<<NP, 256>>>(ET, VE, 0.1f, ve2);

    // sp = node_update(semantic, last=ve2, edge=se)
    agg_kernel<<<dim3(96, KSPLIT), 256>>>(SE, ve2, semantic, Pp, Mp);
    node_kernel<<<NP, 128>>>(Mp, Pp, Wsn, bsn, gsn, betasn, sp);

    // se2 = edge_update(sp, se, temp=10)
    s8_kernel<<<NP, 128>>>(sp, Wse1, S8);
    edge_mlp_kernel<<<dim3(24, 24), 256>>>(sp, Wse1, bse1, Wse2, bse2, S8, ET);
    softmax_edge_kernel<<<NP, 256>>>(ET, SE, 0.1f, se2);
}

// round 15
// speedup vs baseline: 1.7744x; 1.0165x over previous
#include <cuda_runtime.h>
#include <math.h>

#define NP 768
#define DD 128
#define HH 8
#define KSPLIT 8
#define KRANGE (NP / KSPLIT)   // 96

// ---- scratch (no allocs allowed; static device globals) ----
__device__ float g_G [NP*NP];   // visual gram, later reused as edge "e" buffer ET
__device__ float g_G2[NP*NP];   // attribute gram
__device__ float g_VE[NP*NP];
__device__ float g_SE[NP*NP];
__device__ float g_Pp[KSPLIT*NP*DD];   // split-K partials for P
__device__ float g_Mp[KSPLIT*NP*DD];   // split-K partials for M
__device__ float g_S8[NP*HH];
__device__ float g_NR0[NP];
__device__ float g_NR1[NP];

// ---- warp/block reduction helpers (1 barrier per reduction) ----
__device__ __forceinline__ float warp_max(float v) {
#pragma unroll
    for (int o = 16; o > 0; o >>= 1) v = fmaxf(v, __shfl_xor_sync(0xffffffffu, v, o));
    return v;
}
__device__ __forceinline__ float warp_sum(float v) {
#pragma unroll
    for (int o = 16; o > 0; o >>= 1) v += __shfl_xor_sync(0xffffffffu, v, o);
    return v;
}

// ====== symmetric X@X^T for both inputs in one launch (z=0 visual K=128, z=1 attr K=312)
__global__ __launch_bounds__(256) void xxt_sym_kernel(const float* __restrict__ X0,
                                                      const float* __restrict__ X1,
                                                      float* __restrict__ G0,
                                                      float* __restrict__ G1) {
    if (blockIdx.x < blockIdx.y) return;
    int z = blockIdx.z;
    const float* __restrict__ X = z ? X1 : X0;
    float* __restrict__ G = z ? G1 : G0;
    const int K = z ? 312 : 128;

    __shared__ __align__(16) float Xi[16][68];
    __shared__ __align__(16) float Xk[16][68];

    int bi = blockIdx.y * 64, bk = blockIdx.x * 64;
    bool offDiag = (blockIdx.x > blockIdx.y);
    int t = threadIdx.x, tx = t & 15, ty = t >> 4;

    float acc[4][4];
#pragma unroll
    for (int r = 0; r < 4; r++)
#pragma unroll
        for (int c = 0; c < 4; c++) acc[r][c] = 0.f;

    for (int k0 = 0; k0 < K; k0 += 16) {
        for (int idx = t; idx < 1024; idx += 256) {
            int r = idx >> 4, c = idx & 15;
            int kc = k0 + c;
            Xi[c][r] = (kc < K) ? X[(bi + r) * K + kc] : 0.f;
            Xk[c][r] = (kc < K) ? X[(bk + r) * K + kc] : 0.f;
        }
        __syncthreads();
#pragma unroll
        for (int kk = 0; kk < 16; kk++) {
            float4 a = *(const float4*)&Xi[kk][4 * ty];
            float4 b = *(const float4*)&Xk[kk][4 * tx];
            acc[0][0] += a.x * b.x; acc[0][1] += a.x * b.y; acc[0][2] += a.x * b.z; acc[0][3] += a.x * b.w;
            acc[1][0] += a.y * b.x; acc[1][1] += a.y * b.y; acc[1][2] += a.y * b.z; acc[1][3] += a.y * b.w;
            acc[2][0] += a.z * b.x; acc[2][1] += a.z * b.y; acc[2][2] += a.z * b.z; acc[2][3] += a.z * b.w;
            acc[3][0] += a.w * b.x; acc[3][1] += a.w * b.y; acc[3][2] += a.w * b.z; acc[3][3] += a.w * b.w;
        }
        __syncthreads();
    }
    int gk = bk + 4 * tx;
#pragma unroll
    for (int r = 0; r < 4; r++) {
        int gi = bi + 4 * ty + r;
        *(float4*)&G[gi * NP + gk] = make_float4(acc[r][0], acc[r][1], acc[r][2], acc[r][3]);
        if (offDiag) {
            G[(gk + 0) * NP + gi] = acc[r][0];
            G[(gk + 1) * NP + gi] = acc[r][1];
            G[(gk + 2) * NP + gi] = acc[r][2];
            G[(gk + 3) * NP + gi] = acc[r][3];
        }
    }
}

__global__ void norms2_kernel(const float* __restrict__ G0, const float* __restrict__ G1,
                              float* __restrict__ n0, float* __restrict__ n1) {
    int i = blockIdx.x * 256 + threadIdx.x;
    if (i < NP) n0[i] = sqrtf(G0[i * NP + i]);
    else { int j = i - NP; if (j < NP) n1[j] = sqrtf(G1[j * NP + j]); }
}

// ====== cosine-sim softmax for both grams in one launch (grid 768 x 2) ======
__global__ __launch_bounds__(256) void softmax_sim2_kernel(const float* __restrict__ G0,
                                                           const float* __restrict__ G1,
                                                           const float* __restrict__ n0,
                                                           const float* __restrict__ n1,
                                                           float* __restrict__ E0,
                                                           float* __restrict__ E1) {
    __shared__ float shmax[8];
    __shared__ float shsum[8];
    int z = blockIdx.y;
    const float* __restrict__ G = z ? G1 : G0;
    const float* __restrict__ nrm = z ? n1 : n0;
    float* __restrict__ E = z ? E1 : E0;
    const float invtemp = 10.0f;  // 1 / INIT_TEMP

    int i = blockIdx.x, t = threadIdx.x, wid = t >> 5;
    float ni = nrm[i];
    float l[3];
    float mx = -1e30f;
#pragma unroll
    for (int q = 0; q < 3; q++) {
        int c = t + q * 256;
        float den = fmaxf(ni * nrm[c], 1e-8f);
        l[q] = G[i * NP + c] / den * invtemp;
        mx = fmaxf(mx, l[q]);
    }
    mx = warp_max(mx);
    if ((t & 31) == 0) shmax[wid] = mx;
    __syncthreads();
    mx = shmax[0];
#pragma unroll
    for (int w = 1; w < 8; w++) mx = fmaxf(mx, shmax[w]);

    float sum = 0.f;
#pragma unroll
    for (int q = 0; q < 3; q++) { l[q] = expf(l[q] - mx); sum += l[q]; }
    sum = warp_sum(sum);
    if ((t & 31) == 0) shsum[wid] = sum;
    __syncthreads();
    sum = shsum[0];
#pragma unroll
    for (int w = 1; w < 8; w++) sum += shsum[w];
    float inv = 1.f / sum;
#pragma unroll
    for (int q = 0; q < 3; q++) E[i * NP + t + q * 256] = l[q] * inv;
}

// ====== edge softmax: logits = e * (last + eps) * invtemp, fused ======
__global__ __launch_bounds__(256) void softmax_edge_kernel(const float* __restrict__ ET,
                                                           const float* __restrict__ LAST,
                                                           float invtemp,
                                                           float* __restrict__ E) {
    __shared__ float shmax[8];
    __shared__ float shsum[8];
    int i = blockIdx.x, t = threadIdx.x, wid = t >> 5;
    float l[3];
    float mx = -1e30f;
#pragma unroll
    for (int q = 0; q < 3; q++) {
        int c = i * NP + t + q * 256;
        l[q] = ET[c] * (LAST[c] + 1e-8f) * invtemp;
        mx = fmaxf(mx, l[q]);
    }
    mx = warp_max(mx);
    if ((t & 31) == 0) shmax[wid] = mx;
    __syncthreads();
    mx = shmax[0];
#pragma unroll
    for (int w = 1; w < 8; w++) mx = fmaxf(mx, shmax[w]);

    float sum = 0.f;
#pragma unroll
    for (int q = 0; q < 3; q++) { l[q] = expf(l[q] - mx); sum += l[q]; }
    sum = warp_sum(sum);
    if ((t & 31) == 0) shsum[wid] = sum;
    __syncthreads();
    sum = shsum[0];
#pragma unroll
    for (int w = 1; w < 8; w++) sum += shsum[w];
    float inv = 1.f / sum;
#pragma unroll
    for (int q = 0; q < 3; q++) E[i * NP + t + q * 256] = l[q] * inv;
}

// ===== aggregation v5: split-K=8, single V-slice smem load =====
// grid (96, 8). Block = 8 rows x 128 cols over K-range 96.
__global__ __launch_bounds__(256) void agg_kernel(const float* __restrict__ E,
                                                  const float* __restrict__ L,
                                                  const float* __restrict__ V,
                                                  float* __restrict__ Ppart,
                                                  float* __restrict__ Mpart) {
    __shared__ float Et[KRANGE][9];               // [k][row], pad 9
    __shared__ float St[KRANGE][9];               // E + L
    __shared__ __align__(16) float Vs[KRANGE][128];

    int bi = blockIdx.x * 8;
    int kb = blockIdx.y * KRANGE;
    int t = threadIdx.x;
    int tx = t & 31;          // col group: 4 cols each -> 128 cols
    int ty = t >> 5;          // row 0..7 (uniform per warp -> smem broadcast reads)

    // preload E/L rows for this block's K-range, transposed, S = E + L
#pragma unroll
    for (int r = 0; r < 8; r++) {
        for (int k = t; k < KRANGE; k += 256) {
            float e = E[(bi + r) * NP + kb + k];
            float l = L[(bi + r) * NP + kb + k];
            Et[k][r] = e;
            St[k][r] = e + l;
        }
    }
    // load full V slice [KRANGE][128]
    for (int idx = t; idx < KRANGE * 32; idx += 256) {
        int kk = idx >> 5, c4 = idx & 31;
        *(float4*)&Vs[kk][c4 * 4] = *(const float4*)&V[(kb + kk) * DD + c4 * 4];
    }
    __syncthreads();

    float4 p = make_float4(0.f, 0.f, 0.f, 0.f);
    float4 m = make_float4(0.f, 0.f, 0.f, 0.f);

#pragma unroll 16
    for (int kk = 0; kk < KRANGE; kk++) {
        float e = Et[kk][ty];
        float s = St[kk][ty];
        float4 v = *(const float4*)&Vs[kk][4 * tx];
        p.x += e * v.x; p.y += e * v.y; p.z += e * v.z; p.w += e * v.w;
        m.x += s * v.x; m.y += s * v.y; m.z += s * v.z; m.w += s * v.w;
    }
    int row = bi + ty, col = 4 * tx;
    int off = blockIdx.y * NP * DD + row * DD + col;
    *(float4*)&Ppart[off] = p;
    *(float4*)&Mpart[off] = m;
}

// ======== node update: out = relu(LN(M @ W^T + b, g, beta)) + P  ========
// Mi/Pi are KSPLIT-way split-K partials (stride NP*DD); summed here.
__global__ __launch_bounds__(128) void node_kernel(const float* __restrict__ Mi,
                                                   const float* __restrict__ Pi,
                                                   const float* __restrict__ W,
                                                   const float* __restrict__ bv,
                                                   const float* __restrict__ gv,
                                                   const float* __restrict__ bev,
                                                   float* __restrict__ outp) {
    __shared__ float ms[128];
    __shared__ float sh1[4];
    __shared__ float sh2[4];
    int i = blockIdx.x, o = threadIdx.x, wid = o >> 5;
    int idx = i * DD + o;
    float mval = 0.f, pval = 0.f;
#pragma unroll
    for (int q = 0; q < KSPLIT; q++) {
        mval += Mi[idx + q * NP * DD];
        pval += Pi[idx + q * NP * DD];
    }
    ms[o] = mval;
    __syncthreads();
    float acc = bv[o];
    const float4* w4 = (const float4*)(W + o * DD);
    const float4* m4 = (const float4*)ms;
#pragma unroll
    for (int q = 0; q < 32; q++) {
        float4 w = w4[q];
        float4 m = m4[q];
        acc += w.x * m.x + w.y * m.y + w.z * m.z + w.w * m.w;
    }
    float s = warp_sum(acc);
    if ((o & 31) == 0) sh1[wid] = s;
    __syncthreads();
    float mean = (sh1[0] + sh1[1] + sh1[2] + sh1[3]) * (1.f / 128.f);
    float dv = acc - mean;
    float v = warp_sum(dv * dv);
    if ((o & 31) == 0) sh2[wid] = v;
    __syncthreads();
    float var = (sh2[0] + sh2[1] + sh2[2] + sh2[3]) * (1.f / 128.f);
    float y = dv / sqrtf(var + 1e-5f) * gv[o] + bev[o];
    outp[i * DD + o] = fmaxf(y, 0.f) + pval;
}

// ========== S[i][j] = sum_d proto[i][d]^2 * W1[j][d] — one warp per row ==========
__global__ __launch_bounds__(256) void s8_kernel(const float* __restrict__ Pp,
                                                 const float* __restrict__ W1,
                                                 float* __restrict__ S) {
    int wid = threadIdx.x >> 5, lid = threadIdx.x & 31;
    int i = blockIdx.x * 8 + wid;
    // each lane covers d = lid, lid+32, lid+64, lid+96
    float a2[4];
#pragma unroll
    for (int q = 0; q < 4; q++) {
        float a = Pp[i * DD + lid + 32 * q];
        a2[q] = a * a;
    }
    float out[8];
#pragma unroll
    for (int j = 0; j < 8; j++) {
        float v = 0.f;
#pragma unroll
        for (int q = 0; q < 4; q++) v += a2[q] * W1[j * DD + lid + 32 * q];
        out[j] = warp_sum(v);
    }
    if (lid < 8) S[i * HH + lid] = out[lid];
}

// ======= fused edge MLP (symmetric: upper block-triangle only) =======
// writes e = tanh(MLP(pairwise sqdiff)) to ET (symmetric, mirrored)
__global__ __launch_bounds__(256) void edge_mlp_kernel(const float* __restrict__ Pp,
                                                       const float* __restrict__ W1,
                                                       const float* __restrict__ b1,
                                                       const float* __restrict__ W2,
                                                       const float* __restrict__ b2v,
                                                       const float* __restrict__ S,
                                                       float* __restrict__ ET) {
    if (blockIdx.x < blockIdx.y) return;

    __shared__ float Ais[128][33];   // [d][i] transposed tiles
    __shared__ float Aks[128][33];
    __shared__ __align__(16) float W1s[128][8];    // [d][j]
    __shared__ float Sis[32][8];
    __shared__ float Sks[32][8];
    __shared__ float W2s[8];
    __shared__ float b1s[8];
    __shared__ float b2s;

    int bi = blockIdx.y * 32, bk = blockIdx.x * 32;
    bool offDiag = (blockIdx.x > blockIdx.y);
    int t = threadIdx.x;
    for (int idx = t; idx < 4096; idx += 256) {
        int r = idx >> 7, c = idx & 127;
        Ais[c][r] = Pp[(bi + r) * DD + c];
        Aks[c][r] = Pp[(bk + r) * DD + c];
    }
    for (int idx = t; idx < HH * DD; idx += 256)
        W1s[idx & 127][idx >> 7] = W1[idx];
    {
        int r = t >> 3, j = t & 7;
        Sis[r][j] = S[(bi + r) * HH + j];
        Sks[r][j] = S[(bk + r) * HH + j];
    }
    if (t < 8) { W2s[t] = W2[t]; b1s[t] = b1[t]; }
    if (t == 0) b2s = b2v[0];
    __syncthreads();

    int tx = t & 15, ty = t >> 4;
    int i0 = 2 * ty, k0 = 2 * tx;
    float acc[2][2][8];
#pragma unroll
    for (int a = 0; a < 2; a++)
#pragma unroll
        for (int b = 0; b < 2; b++)
#pragma unroll
            for (int j = 0; j < 8; j++) acc[a][b][j] = 0.f;

#pragma unroll 4
    for (int d = 0; d < 128; d++) {
        float4 wa = *(const float4*)&W1s[d][0];
        float4 wb = *(const float4*)&W1s[d][4];
        float w[8] = {wa.x, wa.y, wa.z, wa.w, wb.x, wb.y, wb.z, wb.w};
        float ai0 = Ais[d][i0], ai1 = Ais[d][i0 + 1];
        float ak0 = Aks[d][k0], ak1 = Aks[d][k0 + 1];
        float p00 = ai0 * ak0, p01 = ai0 * ak1;
        float p10 = ai1 * ak0, p11 = ai1 * ak1;
#pragma unroll
        for (int j = 0; j < 8; j++) {
            acc[0][0][j] += p00 * w[j];
            acc[0][1][j] += p01 * w[j];
            acc[1][0][j] += p10 * w[j];
            acc[1][1][j] += p11 * w[j];
        }
    }

#pragma unroll
    for (int ii = 0; ii < 2; ii++)
#pragma unroll
        for (int kk = 0; kk < 2; kk++) {
            int gi = bi + i0 + ii, gk = bk + k0 + kk;
            bool diag = (gi == gk);
            float h[8];
            float mean = 0.f;
#pragma unroll
            for (int j = 0; j < 8; j++) {
                float v = diag ? b1s[j]
                               : (Sis[i0 + ii][j] + Sks[k0 + kk][j] - 2.f * acc[ii][kk][j] + b1s[j]);
                h[j] = v;
                mean += v;
            }
            mean *= 0.125f;
            float var = 0.f;
#pragma unroll
            for (int j = 0; j < 8; j++) { float dv = h[j] - mean; var += dv * dv; }
            var *= 0.125f;
            float inv = 1.f / sqrtf(var + 1e-5f);
            float sdot = b2s;
#pragma unroll
            for (int j = 0; j < 8; j++) {
                float r = fmaxf((h[j] - mean) * inv, 0.f);
                sdot += r * W2s[j];
            }
            float e = tanhf(sdot);
            ET[gi * NP + gk] = e;
            if (offDiag) ET[gk * NP + gi] = e;
        }
}

// ============================== launcher ==============================
extern "C" void kernel_launch(void* const* d_in, const int* in_sizes, int n_in,
                              void* d_out, int out_size) {
    const float* visual   = (const float*)d_in[0];
    const float* semantic = (const float*)d_in[1];
    const float* attr     = (const float*)d_in[2];
    const float* Wvn  = (const float*)d_in[3];
    const float* bvn  = (const float*)d_in[4];
    const float* gvn  = (const float*)d_in[5];
    const float* betavn = (const float*)d_in[6];
    const float* Wve1 = (const float*)d_in[7];
    const float* bve1 = (const float*)d_in[8];
    const float* Wve2 = (const float*)d_in[9];
    const float* bve2 = (const float*)d_in[10];
    const float* Wsn  = (const float*)d_in[11];
    const float* bsn  = (const float*)d_in[12];
    const float* gsn  = (const float*)d_in[13];
    const float* betasn = (const float*)d_in[14];
    const float* Wse1 = (const float*)d_in[15];
    const float* bse1 = (const float*)d_in[16];
    const float* Wse2 = (const float*)d_in[17];
    const float* bse2 = (const float*)d_in[18];

    float* out = (float*)d_out;
    float* vp  = out;                       // [768,128]
    float* sp  = out + NP * DD;             // [768,128]
    float* ve2 = out + 2 * NP * DD;         // [768,768]
    float* se2 = ve2 + NP * NP;             // [768,768]

    float *G, *G2, *VE, *SE, *Pp, *Mp, *S8, *NR0, *NR1;
    cudaGetSymbolAddress((void**)&G,   g_G);
    cudaGetSymbolAddress((void**)&G2,  g_G2);
    cudaGetSymbolAddress((void**)&VE,  g_VE);
    cudaGetSymbolAddress((void**)&SE,  g_SE);
    cudaGetSymbolAddress((void**)&Pp,  g_Pp);
    cudaGetSymbolAddress((void**)&Mp,  g_Mp);
    cudaGetSymbolAddress((void**)&S8,  g_S8);
    cudaGetSymbolAddress((void**)&NR0, g_NR0);
    cudaGetSymbolAddress((void**)&NR1, g_NR1);

    float* ET = G;  // reuse visual gram buffer once VE is computed

    // ve = init_edge(visual, 0.1); se = init_edge(attribute, 0.1) — fused launches
    xxt_sym_kernel<<<dim3(12, 12, 2), 256>>>(visual, attr, G, G2);
    norms2_kernel<<<6, 256>>>(G, G2, NR0, NR1);
    softmax_sim2_kernel<<<dim3(NP, 2), 256>>>(G, G2, NR0, NR1, VE, SE);

    // vp = node_update(visual, last=se, edge=ve)
    agg_kernel<<<dim3(96, KSPLIT), 256>>>(VE, SE, visual, Pp, Mp);
    node_kernel<<<NP, 128>>>(Mp, Pp, Wvn, bvn, gvn, betavn, vp);

    // ve2 = edge_update(vp, ve, temp=10)
    s8_kernel<<<96, 256>>>(vp, Wve1, S8);
    edge_mlp_kernel<<<dim3(24, 24), 256>>>(vp, Wve1, bve1, Wve2, bve2, S8, ET);
    softmax_edge_kernel<<<NP, 256>>>(ET, VE, 0.1f, ve2);

    // sp = node_update(semantic, last=ve2, edge=se)
    agg_kernel<<<dim3(96, KSPLIT), 256>>>(SE, ve2, semantic, Pp, Mp);
    node_kernel<<<NP, 128>>>(Mp, Pp, Wsn, bsn, gsn, betasn, sp);

    // se2 = edge_update(sp, se, temp=10)
    s8_kernel<<<96, 256>>>(sp, Wse1, S8);
    edge_mlp_kernel<<<dim3(24, 24), 256>>>(sp, Wse1, bse1, Wse2, bse2, S8, ET);
    softmax_edge_kernel<<<NP, 256>>>(ET, SE, 0.1f, se2);
}